// round 16
// baseline (speedup 1.0000x reference)
#include <cuda_runtime.h>
#include <cuda_fp16.h>
#include <cstdint>

#define STARTP 4080

// ---------------------------------------------------------------------------
// Device-global scratch (no allocations allowed)
// ---------------------------------------------------------------------------
__device__ float g_qkv[256 * 6144];                 // fp32 q|k|v (post-RoPE)
__device__ __half g_x_h [256*4096];                 // x, single fp16 plane
__device__ __half g_at_h[256*4096];                 // attn out, single fp16 plane

// ---------------------------------------------------------------------------
// helpers
// ---------------------------------------------------------------------------
// fp16 split: hi plane + residual lo plane (residual exact to ~2^-22)
__device__ __forceinline__ void split2h(float a, float b, uint32_t& h, uint32_t& l) {
    __half2 p = __floats2half2_rn(a, b);
    float ra = a - __half2float(__low2half(p));
    float rb = b - __half2float(__high2half(p));
    __half2 q = __floats2half2_rn(ra, rb);
    h = *(uint32_t*)&p;
    l = *(uint32_t*)&q;
}
__device__ __forceinline__ uint32_t packh(float a, float b) {   // a->lo16, b->hi16
    __half2 p = __floats2half2_rn(a, b);
    return *(uint32_t*)&p;
}

__device__ __forceinline__ void mma16h(float* c, const uint32_t* a,
                                       uint32_t b0, uint32_t b1) {
    asm("mma.sync.aligned.m16n8k16.row.col.f32.f16.f16.f32 "
        "{%0,%1,%2,%3}, {%4,%5,%6,%7}, {%8,%9}, {%0,%1,%2,%3};"
        : "+f"(c[0]), "+f"(c[1]), "+f"(c[2]), "+f"(c[3])
        : "r"(a[0]), "r"(a[1]), "r"(a[2]), "r"(a[3]), "r"(b0), "r"(b1));
}

__device__ __forceinline__ void ldsm4(uint32_t* r, uint32_t addr) {
    asm volatile("ldmatrix.sync.aligned.m8n8.x4.shared.b16 {%0,%1,%2,%3}, [%4];"
        : "=r"(r[0]), "=r"(r[1]), "=r"(r[2]), "=r"(r[3]) : "r"(addr));
}
__device__ __forceinline__ void ldsm4t(uint32_t* r, uint32_t addr) {
    asm volatile("ldmatrix.sync.aligned.m8n8.x4.trans.shared.b16 {%0,%1,%2,%3}, [%4];"
        : "=r"(r[0]), "=r"(r[1]), "=r"(r[2]), "=r"(r[3]) : "r"(addr));
}
__device__ __forceinline__ void cp16(uint32_t s, const void* g) {
    asm volatile("cp.async.cg.shared.global [%0], [%1], 16;" :: "r"(s), "l"(g));
}

// ---------------------------------------------------------------------------
// fp32 -> single fp16 plane (only for x: 4 MB)
// ---------------------------------------------------------------------------
__global__ __launch_bounds__(256) void convert_kernel(
    const float* __restrict__ in, __half* __restrict__ oh, int n4)
{
    int i = blockIdx.x * 256 + threadIdx.x;
    if (i >= n4) return;
    float4 v = ((const float4*)in)[i];
    ((uint2*)oh)[i] = make_uint2(packh(v.x, v.y), packh(v.z, v.w));
}

// ---------------------------------------------------------------------------
// fp16x2 GEMM (R13 winner, verbatim): C = A @ B + bias.
// A: single fp16 plane. B: fp32, register-prefetched + split hi/lo in-loop.
// Block 64M x 64N, BK=32, 128 thr (warps 2m x 2n), 2-stage smem.
// ---------------------------------------------------------------------------
template<bool ROPE>
__global__ __launch_bounds__(128) void gemm_f16x2(
    const __half* __restrict__ Ah,
    const float* B0, int ldb0, const float* bias0, int split1,
    const float* B1, int ldb1, const float* bias1, int split2_,
    const float* B2, int ldb2, const float* bias2,
    float* __restrict__ C, int ldc,
    const float* __restrict__ cos_t, const float* __restrict__ sin_t)
{
    constexpr int BN = 64, BSTR = 72, NV4 = 16, LB = 4, NF = 4, NG = 2;

    extern __shared__ char smraw[];
    __half* As = (__half*)smraw;            // [2][64][40]
    __half* Bs = As + 2*64*40;              // [2][2][32][72]

    const int n0 = blockIdx.x * BN;
    const int m0 = blockIdx.y * 64;

    const float* Bp; int ldb; const float* bias; int nloc;
    if (n0 < split1)       { Bp = B0; ldb = ldb0; bias = bias0; nloc = n0; }
    else if (n0 < split2_) { Bp = B1; ldb = ldb1; bias = bias1; nloc = n0 - split1; }
    else                   { Bp = B2; ldb = ldb2; bias = bias2; nloc = n0 - split2_; }

    const int tid = threadIdx.x, lane = tid & 31, warp = tid >> 5;
    const int g = lane >> 2, tig = lane & 3;
    const int wm = warp & 1, wn = warp >> 1;
    const int lr = lane & 7, mt = lane >> 3;

    const uint32_t sA = (uint32_t)__cvta_generic_to_shared(As);
    const uint32_t sB = (uint32_t)__cvta_generic_to_shared(Bs);

    uint4  pa[2];
    float4 pb[LB];

    auto fetch = [&](int ck) {
        #pragma unroll
        for (int i = 0; i < 2; ++i) {
            int idx = tid + 128 * i;
            int row = idx >> 2, seg = idx & 3;
            pa[i] = *(const uint4*)(Ah + (size_t)(m0 + row) * 4096 + ck * 32 + seg * 8);
        }
        #pragma unroll
        for (int i = 0; i < LB; ++i) {
            int idx = tid + 128 * i;
            int row = idx / NV4, c4 = idx % NV4;
            pb[i] = *(const float4*)(Bp + (size_t)(ck * 32 + row) * ldb + nloc + c4 * 4);
        }
    };

    float acc[2][NF][4];
    #pragma unroll
    for (int mf = 0; mf < 2; ++mf)
        #pragma unroll
        for (int nf = 0; nf < NF; ++nf)
            #pragma unroll
            for (int j = 0; j < 4; ++j) acc[mf][nf][j] = 0.f;

    fetch(0);

    for (int ck = 0; ck < 128; ++ck) {
        const int s = ck & 1;

        #pragma unroll
        for (int i = 0; i < 2; ++i) {
            int idx = tid + 128 * i;
            int row = idx >> 2, seg = idx & 3;
            *(uint4*)&As[(s*64 + row)*40 + seg*8] = pa[i];
        }
        #pragma unroll
        for (int i = 0; i < LB; ++i) {
            int idx = tid + 128 * i;
            int row = idx / NV4, c4 = idx % NV4;
            float4 v = pb[i];
            uint32_t h0, l0, h1, l1;
            split2h(v.x, v.y, h0, l0);
            split2h(v.z, v.w, h1, l1);
            *(uint2*)&Bs[((s*2 + 0)*32 + row)*BSTR + c4*4] = make_uint2(h0, h1);
            *(uint2*)&Bs[((s*2 + 1)*32 + row)*BSTR + c4*4] = make_uint2(l0, l1);
        }

        if (ck + 1 < 128) fetch(ck + 1);
        __syncthreads();

        #pragma unroll
        for (int ks = 0; ks < 2; ++ks) {
            int k0 = ks * 16;
            uint32_t ah[2][4];
            #pragma unroll
            for (int mf = 0; mf < 2; ++mf) {
                int row = wm*32 + mf*16 + (mt & 1)*8 + lr;
                int col = k0 + (mt >> 1)*8;
                ldsm4(ah[mf], sA + (uint32_t)(((s*64 + row)*40 + col)*2));
            }
            #pragma unroll
            for (int ng = 0; ng < NG; ++ng) {
                int brow = k0 + (mt & 1)*8 + lr;
                int bcol = wn*(BN/2) + ng*16 + (mt >> 1)*8;
                uint32_t bh[4], bl[4];
                ldsm4t(bh, sB + (uint32_t)((((s*2+0)*32 + brow)*BSTR + bcol)*2));
                ldsm4t(bl, sB + (uint32_t)((((s*2+1)*32 + brow)*BSTR + bcol)*2));
                #pragma unroll
                for (int h = 0; h < 2; ++h) {
                    int nf = ng*2 + h;
                    #pragma unroll
                    for (int mf = 0; mf < 2; ++mf) {
                        mma16h(acc[mf][nf], ah[mf], bh[2*h], bh[2*h+1]);
                        mma16h(acc[mf][nf], ah[mf], bl[2*h], bl[2*h+1]);
                    }
                }
            }
        }
    }

    __syncthreads();
    #pragma unroll
    for (int mf = 0; mf < 2; ++mf) {
        int r0 = m0 + wm*32 + mf*16 + g;
        #pragma unroll
        for (int nf = 0; nf < NF; ++nf) {
            int cl = wn*(BN/2) + nf*8 + 2*tig;
            int gc = n0 + cl;
            float b0v = bias[nloc + cl], b1v = bias[nloc + cl + 1];
            float c0 = acc[mf][nf][0] + b0v, c1 = acc[mf][nf][1] + b1v;
            float c2 = acc[mf][nf][2] + b0v, c3 = acc[mf][nf][3] + b1v;
            if (ROPE && gc < 5120) {
                int p = (gc & 127) >> 1;
                float cs0 = cos_t[(r0 & 15)*64 + p],       sn0 = sin_t[(r0 & 15)*64 + p];
                float cs1 = cos_t[((r0 + 8) & 15)*64 + p], sn1 = sin_t[((r0 + 8) & 15)*64 + p];
                float t0 = c0*cs0 - c1*sn0, t1 = c0*sn0 + c1*cs0;
                float t2 = c2*cs1 - c3*sn1, t3 = c2*sn1 + c3*cs1;
                c0 = t0; c1 = t1; c2 = t2; c3 = t3;
            }
            *(float2*)(C + (size_t)r0 * ldc + gc)       = make_float2(c0, c1);
            *(float2*)(C + (size_t)(r0 + 8) * ldc + gc) = make_float2(c2, c3);
        }
    }
}

// ---------------------------------------------------------------------------
// fp16x2 flash attention, 384 threads: 4 consumer warps (R14 fp16 math:
// Q single plane, K/V hi-lo splits, P single plane) + 8 PRODUCER warps
// (conversion work halved per warp — producers were the tile bottleneck).
// ---------------------------------------------------------------------------
__global__ __launch_bounds__(384, 1) void attn_f16x2(
    const float* __restrict__ cache_k, const float* __restrict__ cache_v)
{
    extern __shared__ char smraw[];
    __half* Kh = (__half*)smraw;                    // [2][64][136]
    __half* Kl = Kh + 2*8704;
    __half* Vh = Kl + 2*8704;
    __half* Vl = Vh + 2*8704;                       // planes end at 139264 B
    float* Kst = (float*)(smraw + 139264);          // staging [64][128] fp32
    float* Vst = (float*)(smraw + 172032);          // staging [64][128] fp32
    float* Qs  = (float*)smraw;                     // staging only (pre-loop)

    const int tid = threadIdx.x, lane = tid & 31, w = tid >> 5;
    const int g = lane >> 2, tig = lane & 3;
    const int lr = lane & 7, mt = lane >> 3;
    const int b = blockIdx.x >> 3, kvh = blockIdx.x & 7;
    const int ptid = tid - 128;                     // producer linear id 0..255
    const float scale = 0.08838834764831843f;       // 1/sqrt(128)
    const float* qkv = g_qkv;

    const uint32_t stk_b = (uint32_t)__cvta_generic_to_shared(Kst);
    const uint32_t stv_b = (uint32_t)__cvta_generic_to_shared(Vst);

    // producers (256 threads): fire cp.async for K/V tile t into staging
    auto issue = [&](int t) {
        #pragma unroll
        for (int i = 0; i < 8; ++i) {
            int id = ptid + 256 * i;                // 0..2047
            int row = id >> 5, c4 = (id & 31) << 2;
            int key = t * 64 + row;
            const float *ks, *vs;
            if (key < STARTP) {
                size_t base = ((size_t)(b * 4096 + key) * 8 + kvh) * 128 + c4;
                ks = cache_k + base; vs = cache_v + base;
            } else {
                size_t rb = (size_t)(b * 16 + key - STARTP) * 6144 + kvh * 128 + c4;
                ks = qkv + rb + 4096; vs = qkv + rb + 5120;
            }
            uint32_t off = (uint32_t)((row * 128 + c4) * 4);
            cp16(stk_b + off, ks);
            cp16(stv_b + off, vs);
        }
        asm volatile("cp.async.commit_group;");
    };
    // producers: convert staged fp32 tile -> fp16 hi/lo planes (stage t&1)
    auto convert = [&](int t) {
        int s = t & 1;
        #pragma unroll
        for (int i = 0; i < 8; ++i) {
            int id = ptid + 256 * i;
            int row = id >> 5, c4 = (id & 31) << 2;
            float4 kv = *(const float4*)&Kst[row * 128 + c4];
            float4 vv = *(const float4*)&Vst[row * 128 + c4];
            uint32_t h0, l0, h1, l1;
            int e = s * 8704 + row * 136 + c4;
            split2h(kv.x, kv.y, h0, l0); split2h(kv.z, kv.w, h1, l1);
            *(uint32_t*)&Kh[e] = h0; *(uint32_t*)&Kh[e + 2] = h1;
            *(uint32_t*)&Kl[e] = l0; *(uint32_t*)&Kl[e + 2] = l1;
            split2h(vv.x, vv.y, h0, l0); split2h(vv.z, vv.w, h1, l1);
            *(uint32_t*)&Vh[e] = h0; *(uint32_t*)&Vh[e + 2] = h1;
            *(uint32_t*)&Vl[e] = l0; *(uint32_t*)&Vl[e + 2] = l1;
        }
    };

    if (w >= 4) issue(0);

    // consumers stage Q (scaled fp32) into the planes-aliased region
    if (w < 4) {
        for (int i = tid; i < 64 * 32; i += 128) {
            int r = i >> 5, c4 = (i & 31) << 2;
            const float* src = qkv + (size_t)(b * 16 + (r & 15)) * 6144
                             + (kvh * 4 + (r >> 4)) * 128 + c4;
            float4 v = *(const float4*)src;
            Qs[r * 132 + c4 + 0] = v.x * scale;
            Qs[r * 132 + c4 + 1] = v.y * scale;
            Qs[r * 132 + c4 + 2] = v.z * scale;
            Qs[r * 132 + c4 + 3] = v.w * scale;
        }
    }
    __syncthreads();

    // consumers lift Q to single fp16 fragments
    uint32_t qf[8][4];
    if (w < 4) {
        #pragma unroll
        for (int kk = 0; kk < 8; ++kk) {
            const float* r0 = Qs + (w*16 + g    ) * 132 + kk*16;
            const float* r1 = Qs + (w*16 + g + 8) * 132 + kk*16;
            qf[kk][0] = packh(r0[2*tig],     r0[2*tig + 1]);
            qf[kk][1] = packh(r1[2*tig],     r1[2*tig + 1]);
            qf[kk][2] = packh(r0[2*tig + 8], r0[2*tig + 9]);
            qf[kk][3] = packh(r1[2*tig + 8], r1[2*tig + 9]);
        }
    }
    __syncthreads();   // Qs reads done; planes region free for conversion

    if (w >= 4) {
        asm volatile("cp.async.wait_group 0;");
        convert(0);
        issue(1);
    }
    __syncthreads();   // stage 0 planes visible

    const uint32_t kh_b = (uint32_t)__cvta_generic_to_shared(Kh);
    const uint32_t kl_b = (uint32_t)__cvta_generic_to_shared(Kl);
    const uint32_t vh_b = (uint32_t)__cvta_generic_to_shared(Vh);
    const uint32_t vl_b = (uint32_t)__cvta_generic_to_shared(Vl);

    float oacc[16][4];
    #pragma unroll
    for (int i = 0; i < 16; ++i)
        #pragma unroll
        for (int j = 0; j < 4; ++j) oacc[i][j] = 0.f;
    float mA = -1e30f, mB = -1e30f, lA = 0.f, lB = 0.f;

    for (int t = 0; t < 64; ++t) {
        const int s = t & 1;

        if (w >= 4) {
            if (t + 1 < 64) {
                asm volatile("cp.async.wait_group 0;");
                convert(t + 1);
                if (t + 2 < 64) issue(t + 2);
            }
        } else {
            // ---- S = Q K^T (16 rows x 64 keys), 2 MMAs per fragment ----
            float sacc[8][4];
            #pragma unroll
            for (int nf = 0; nf < 8; ++nf)
                #pragma unroll
                for (int j = 0; j < 4; ++j) sacc[nf][j] = 0.f;

            #pragma unroll
            for (int kk = 0; kk < 8; ++kk) {
                #pragma unroll
                for (int nfp = 0; nfp < 4; ++nfp) {
                    int row = (nfp*2 + (mt >> 1))*8 + lr;
                    int col = kk*16 + (mt & 1)*8;
                    uint32_t off = (uint32_t)((s*8704 + row*136 + col)*2);
                    uint32_t bh[4], bl[4];
                    ldsm4(bh, kh_b + off);
                    ldsm4(bl, kl_b + off);
                    #pragma unroll
                    for (int h = 0; h < 2; ++h) {
                        int nf = nfp*2 + h;
                        mma16h(sacc[nf], qf[kk], bh[2*h], bh[2*h+1]);
                        mma16h(sacc[nf], qf[kk], bl[2*h], bl[2*h+1]);
                    }
                }
            }

            if (t == 63) {  // causal mask, analytic
                #pragma unroll
                for (int nf = 0; nf < 8; ++nf) {
                    int key = 4032 + nf * 8 + 2 * tig;
                    if (key     > STARTP + g)     sacc[nf][0] = -1e30f;
                    if (key + 1 > STARTP + g)     sacc[nf][1] = -1e30f;
                    if (key     > STARTP + g + 8) sacc[nf][2] = -1e30f;
                    if (key + 1 > STARTP + g + 8) sacc[nf][3] = -1e30f;
                }
            }

            // ---- online softmax (rows g and g+8) ----
            float tmA = -1e30f, tmB = -1e30f;
            #pragma unroll
            for (int nf = 0; nf < 8; ++nf) {
                tmA = fmaxf(tmA, fmaxf(sacc[nf][0], sacc[nf][1]));
                tmB = fmaxf(tmB, fmaxf(sacc[nf][2], sacc[nf][3]));
            }
            tmA = fmaxf(tmA, __shfl_xor_sync(0xffffffffu, tmA, 1));
            tmA = fmaxf(tmA, __shfl_xor_sync(0xffffffffu, tmA, 2));
            tmB = fmaxf(tmB, __shfl_xor_sync(0xffffffffu, tmB, 1));
            tmB = fmaxf(tmB, __shfl_xor_sync(0xffffffffu, tmB, 2));

            float mnA = fmaxf(mA, tmA), mnB = fmaxf(mB, tmB);
            float cA = __expf(mA - mnA), cB = __expf(mB - mnB);
            float psA = 0.f, psB = 0.f;
            #pragma unroll
            for (int nf = 0; nf < 8; ++nf) {
                sacc[nf][0] = __expf(sacc[nf][0] - mnA);
                sacc[nf][1] = __expf(sacc[nf][1] - mnA);
                sacc[nf][2] = __expf(sacc[nf][2] - mnB);
                sacc[nf][3] = __expf(sacc[nf][3] - mnB);
                psA += sacc[nf][0] + sacc[nf][1];
                psB += sacc[nf][2] + sacc[nf][3];
            }
            psA += __shfl_xor_sync(0xffffffffu, psA, 1);
            psA += __shfl_xor_sync(0xffffffffu, psA, 2);
            psB += __shfl_xor_sync(0xffffffffu, psB, 1);
            psB += __shfl_xor_sync(0xffffffffu, psB, 2);
            lA = lA * cA + psA; lB = lB * cB + psB;
            mA = mnA; mB = mnB;
            #pragma unroll
            for (int i = 0; i < 16; ++i) {
                oacc[i][0] *= cA; oacc[i][1] *= cA;
                oacc[i][2] *= cB; oacc[i][3] *= cB;
            }

            // ---- O += P V (P single fp16, V hi/lo), 2 MMAs per fragment ----
            #pragma unroll
            for (int kf = 0; kf < 4; ++kf) {
                uint32_t pf[4];
                pf[0] = packh(sacc[2*kf][0],   sacc[2*kf][1]);
                pf[1] = packh(sacc[2*kf][2],   sacc[2*kf][3]);
                pf[2] = packh(sacc[2*kf+1][0], sacc[2*kf+1][1]);
                pf[3] = packh(sacc[2*kf+1][2], sacc[2*kf+1][3]);
                #pragma unroll
                for (int np = 0; np < 8; ++np) {
                    int row = kf*16 + (mt & 1)*8 + lr;
                    int col = (np*2 + (mt >> 1))*8;
                    uint32_t off = (uint32_t)((s*8704 + row*136 + col)*2);
                    uint32_t vh[4], vl[4];
                    ldsm4t(vh, vh_b + off);
                    ldsm4t(vl, vl_b + off);
                    #pragma unroll
                    for (int h = 0; h < 2; ++h) {
                        int nf2 = np*2 + h;
                        mma16h(oacc[nf2], pf, vh[2*h], vh[2*h+1]);
                        mma16h(oacc[nf2], pf, vl[2*h], vl[2*h+1]);
                    }
                }
            }
        }
        __syncthreads();   // stage s consumed; stage s^1 stores visible
    }

    // ---- finalize: single fp16 plane feeding the out-projection ----
    if (w < 4) {
        float rAi = 1.f / lA, rBi = 1.f / lB;
        size_t baseA = (size_t)(b*16 + g    ) * 4096 + (kvh*4 + w) * 128;
        size_t baseB = (size_t)(b*16 + g + 8) * 4096 + (kvh*4 + w) * 128;
        #pragma unroll
        for (int nf2 = 0; nf2 < 16; ++nf2) {
            int col = nf2*8 + 2*tig;
            *(uint32_t*)&g_at_h[baseA + col] =
                packh(oacc[nf2][0]*rAi, oacc[nf2][1]*rAi);
            *(uint32_t*)&g_at_h[baseB + col] =
                packh(oacc[nf2][2]*rBi, oacc[nf2][3]*rBi);
        }
    }
}

// ---------------------------------------------------------------------------
extern "C" void kernel_launch(void* const* d_in, const int* in_sizes, int n_in,
                              void* d_out, int out_size)
{
    const float* x  = (const float*)d_in[0];
    const float* fc = (const float*)d_in[1];
    const float* fs = (const float*)d_in[2];
    const float* ck = (const float*)d_in[4];
    const float* cv = (const float*)d_in[5];
    const float* wq = (const float*)d_in[6];
    const float* bq = (const float*)d_in[7];
    const float* wk = (const float*)d_in[8];
    const float* bk = (const float*)d_in[9];
    const float* wv = (const float*)d_in[10];
    const float* bv = (const float*)d_in[11];
    const float* wo = (const float*)d_in[12];
    const float* bo = (const float*)d_in[13];
    float* out = (float*)d_out;

    __half *x_h, *at_h;
    float* qkv;
    cudaGetSymbolAddress((void**)&x_h,  g_x_h);
    cudaGetSymbolAddress((void**)&at_h, g_at_h);
    cudaGetSymbolAddress((void**)&qkv,  g_qkv);

    const int gemm_smem = (2*64*40 + 2*2*32*72) * 2;      // 28672 B
    const int attn_smem = 139264 + 2 * 32768;             // 204800 B
    cudaFuncSetAttribute(gemm_f16x2<true>,
                         cudaFuncAttributeMaxDynamicSharedMemorySize, gemm_smem);
    cudaFuncSetAttribute(gemm_f16x2<false>,
                         cudaFuncAttributeMaxDynamicSharedMemorySize, gemm_smem);
    cudaFuncSetAttribute(attn_f16x2,
                         cudaFuncAttributeMaxDynamicSharedMemorySize, attn_smem);

    // 1) x -> single fp16 plane
    convert_kernel<<<1024, 256>>>(x, x_h, 256*4096/4);

    // 2) fused QKV projection + RoPE (fp16x2; fp32 out into g_qkv); 384 blocks
    gemm_f16x2<true><<<dim3(96, 4), 128, gemm_smem>>>(
        x_h,
        wq, 4096, bq, 4096,
        wk, 1024, bk, 5120,
        wv, 1024, bv,
        qkv, 6144, fc, fs);

    // 3) attention (fp16x2; 4 consumer + 8 producer warps; writes fp16 plane)
    attn_f16x2<<<128, 384, attn_smem>>>(ck, cv);

    // 4) output projection (fp16x2) -> d_out; 256 blocks
    gemm_f16x2<false><<<dim3(64, 4), 128, gemm_smem>>>(
        at_h,
        wo, 4096, bo, 1 << 30,
        wo, 4096, bo, 1 << 30,
        wo, 4096, bo,
        out, 4096, nullptr, nullptr);
}

// round 17
// speedup vs baseline: 1.1504x; 1.1504x over previous
#include <cuda_runtime.h>
#include <cuda_bf16.h>
#include <cuda_fp16.h>
#include <cstdint>

#define STARTP 4080

// ---------------------------------------------------------------------------
// Device-global scratch (no allocations allowed)
// ---------------------------------------------------------------------------
__device__ float g_qkv[256 * 6144];                 // fp32 q|k|v (post-RoPE)
__device__ __half g_x_h [256*4096];                 // x, single fp16 plane
__device__ __half g_at_h[256*4096];                 // attn out, single fp16 plane

// ---------------------------------------------------------------------------
// helpers
// ---------------------------------------------------------------------------
__device__ __forceinline__ uint32_t packbf(float a, float b) {  // a->lo16, b->hi16
    uint32_t u;
    asm("cvt.rn.bf16x2.f32 %0, %1, %2;" : "=r"(u) : "f"(b), "f"(a));
    return u;
}
// bf16 split (attention): hi plane + residual lo plane
__device__ __forceinline__ void split2(float a, float b, uint32_t& h, uint32_t& l) {
    h = packbf(a, b);
    float ra = a - __uint_as_float(h << 16);
    float rb = b - __uint_as_float(h & 0xffff0000u);
    l = packbf(ra, rb);
}
__device__ __forceinline__ uint32_t packh(float a, float b) {   // a->lo16, b->hi16
    __half2 p = __floats2half2_rn(a, b);
    return *(uint32_t*)&p;
}

__device__ __forceinline__ void mma16(float* c, const uint32_t* a,
                                      uint32_t b0, uint32_t b1) {
    asm("mma.sync.aligned.m16n8k16.row.col.f32.bf16.bf16.f32 "
        "{%0,%1,%2,%3}, {%4,%5,%6,%7}, {%8,%9}, {%0,%1,%2,%3};"
        : "+f"(c[0]), "+f"(c[1]), "+f"(c[2]), "+f"(c[3])
        : "r"(a[0]), "r"(a[1]), "r"(a[2]), "r"(a[3]), "r"(b0), "r"(b1));
}
__device__ __forceinline__ void mma16h(float* c, const uint32_t* a,
                                       uint32_t b0, uint32_t b1) {
    asm("mma.sync.aligned.m16n8k16.row.col.f32.f16.f16.f32 "
        "{%0,%1,%2,%3}, {%4,%5,%6,%7}, {%8,%9}, {%0,%1,%2,%3};"
        : "+f"(c[0]), "+f"(c[1]), "+f"(c[2]), "+f"(c[3])
        : "r"(a[0]), "r"(a[1]), "r"(a[2]), "r"(a[3]), "r"(b0), "r"(b1));
}

__device__ __forceinline__ void ldsm4(uint32_t* r, uint32_t addr) {
    asm volatile("ldmatrix.sync.aligned.m8n8.x4.shared.b16 {%0,%1,%2,%3}, [%4];"
        : "=r"(r[0]), "=r"(r[1]), "=r"(r[2]), "=r"(r[3]) : "r"(addr));
}
__device__ __forceinline__ void ldsm4t(uint32_t* r, uint32_t addr) {
    asm volatile("ldmatrix.sync.aligned.m8n8.x4.trans.shared.b16 {%0,%1,%2,%3}, [%4];"
        : "=r"(r[0]), "=r"(r[1]), "=r"(r[2]), "=r"(r[3]) : "r"(addr));
}
__device__ __forceinline__ void cp16(uint32_t s, const void* g) {
    asm volatile("cp.async.cg.shared.global [%0], [%1], 16;" :: "r"(s), "l"(g));
}

// ---------------------------------------------------------------------------
// fp32 -> single fp16 plane (only for x: 4 MB)
// ---------------------------------------------------------------------------
__global__ __launch_bounds__(256) void convert_kernel(
    const float* __restrict__ in, __half* __restrict__ oh, int n4)
{
    int i = blockIdx.x * 256 + threadIdx.x;
    if (i >= n4) return;
    float4 v = ((const float4*)in)[i];
    ((uint2*)oh)[i] = make_uint2(packh(v.x, v.y), packh(v.z, v.w));
}

// ---------------------------------------------------------------------------
// fp16x1 GEMM: C[M,N] = A @ B + bias. A: single fp16 plane. B: fp32 ->
// single fp16 plane in-loop (one rounding site per weight matrix).
// 1 MMA / 1 B-ldsm / 1 STS-pair per product — every pipe halves vs fp16x2.
// Block 64M x 64N, BK=32, 128 thr (warps 2m x 2n), 2-stage smem.
// Optional fused RoPE epilogue (QKV projection: global cols < 5120).
// ---------------------------------------------------------------------------
template<bool ROPE>
__global__ __launch_bounds__(128) void gemm_f16x1(
    const __half* __restrict__ Ah,
    const float* B0, int ldb0, const float* bias0, int split1,
    const float* B1, int ldb1, const float* bias1, int split2_,
    const float* B2, int ldb2, const float* bias2,
    float* __restrict__ C, int ldc,
    const float* __restrict__ cos_t, const float* __restrict__ sin_t)
{
    constexpr int BN = 64, BSTR = 72, NV4 = 16, LB = 4, NF = 4, NG = 2;

    extern __shared__ char smraw[];
    __half* As = (__half*)smraw;            // [2][64][40]
    __half* Bs = As + 2*64*40;              // [2][32][72]

    const int n0 = blockIdx.x * BN;
    const int m0 = blockIdx.y * 64;

    const float* Bp; int ldb; const float* bias; int nloc;
    if (n0 < split1)       { Bp = B0; ldb = ldb0; bias = bias0; nloc = n0; }
    else if (n0 < split2_) { Bp = B1; ldb = ldb1; bias = bias1; nloc = n0 - split1; }
    else                   { Bp = B2; ldb = ldb2; bias = bias2; nloc = n0 - split2_; }

    const int tid = threadIdx.x, lane = tid & 31, warp = tid >> 5;
    const int g = lane >> 2, tig = lane & 3;
    const int wm = warp & 1, wn = warp >> 1;
    const int lr = lane & 7, mt = lane >> 3;

    const uint32_t sA = (uint32_t)__cvta_generic_to_shared(As);
    const uint32_t sB = (uint32_t)__cvta_generic_to_shared(Bs);

    uint4  pa[2];
    float4 pb[LB];

    auto fetch = [&](int ck) {
        #pragma unroll
        for (int i = 0; i < 2; ++i) {
            int idx = tid + 128 * i;
            int row = idx >> 2, seg = idx & 3;
            pa[i] = *(const uint4*)(Ah + (size_t)(m0 + row) * 4096 + ck * 32 + seg * 8);
        }
        #pragma unroll
        for (int i = 0; i < LB; ++i) {
            int idx = tid + 128 * i;
            int row = idx / NV4, c4 = idx % NV4;
            pb[i] = *(const float4*)(Bp + (size_t)(ck * 32 + row) * ldb + nloc + c4 * 4);
        }
    };

    float acc[2][NF][4];
    #pragma unroll
    for (int mf = 0; mf < 2; ++mf)
        #pragma unroll
        for (int nf = 0; nf < NF; ++nf)
            #pragma unroll
            for (int j = 0; j < 4; ++j) acc[mf][nf][j] = 0.f;

    fetch(0);

    for (int ck = 0; ck < 128; ++ck) {
        const int s = ck & 1;

        #pragma unroll
        for (int i = 0; i < 2; ++i) {
            int idx = tid + 128 * i;
            int row = idx >> 2, seg = idx & 3;
            *(uint4*)&As[(s*64 + row)*40 + seg*8] = pa[i];
        }
        #pragma unroll
        for (int i = 0; i < LB; ++i) {
            int idx = tid + 128 * i;
            int row = idx / NV4, c4 = idx % NV4;
            float4 v = pb[i];
            *(uint2*)&Bs[(s*32 + row)*BSTR + c4*4] =
                make_uint2(packh(v.x, v.y), packh(v.z, v.w));
        }

        if (ck + 1 < 128) fetch(ck + 1);
        __syncthreads();

        #pragma unroll
        for (int ks = 0; ks < 2; ++ks) {
            int k0 = ks * 16;
            uint32_t ah[2][4];
            #pragma unroll
            for (int mf = 0; mf < 2; ++mf) {
                int row = wm*32 + mf*16 + (mt & 1)*8 + lr;
                int col = k0 + (mt >> 1)*8;
                ldsm4(ah[mf], sA + (uint32_t)(((s*64 + row)*40 + col)*2));
            }
            #pragma unroll
            for (int ng = 0; ng < NG; ++ng) {
                int brow = k0 + (mt & 1)*8 + lr;
                int bcol = wn*(BN/2) + ng*16 + (mt >> 1)*8;
                uint32_t bh[4];
                ldsm4t(bh, sB + (uint32_t)(((s*32 + brow)*BSTR + bcol)*2));
                #pragma unroll
                for (int h = 0; h < 2; ++h) {
                    int nf = ng*2 + h;
                    #pragma unroll
                    for (int mf = 0; mf < 2; ++mf)
                        mma16h(acc[mf][nf], ah[mf], bh[2*h], bh[2*h+1]);
                }
            }
        }
    }

    __syncthreads();
    #pragma unroll
    for (int mf = 0; mf < 2; ++mf) {
        int r0 = m0 + wm*32 + mf*16 + g;
        #pragma unroll
        for (int nf = 0; nf < NF; ++nf) {
            int cl = wn*(BN/2) + nf*8 + 2*tig;
            int gc = n0 + cl;
            float b0v = bias[nloc + cl], b1v = bias[nloc + cl + 1];
            float c0 = acc[mf][nf][0] + b0v, c1 = acc[mf][nf][1] + b1v;
            float c2 = acc[mf][nf][2] + b0v, c3 = acc[mf][nf][3] + b1v;
            if (ROPE && gc < 5120) {
                int p = (gc & 127) >> 1;
                float cs0 = cos_t[(r0 & 15)*64 + p],       sn0 = sin_t[(r0 & 15)*64 + p];
                float cs1 = cos_t[((r0 + 8) & 15)*64 + p], sn1 = sin_t[((r0 + 8) & 15)*64 + p];
                float t0 = c0*cs0 - c1*sn0, t1 = c0*sn0 + c1*cs0;
                float t2 = c2*cs1 - c3*sn1, t3 = c2*sn1 + c3*cs1;
                c0 = t0; c1 = t1; c2 = t2; c3 = t3;
            }
            *(float2*)(C + (size_t)r0 * ldc + gc)       = make_float2(c0, c1);
            *(float2*)(C + (size_t)(r0 + 8) * ldc + gc) = make_float2(c2, c3);
        }
    }
}

// ---------------------------------------------------------------------------
// bf16x3 flash attention (R13 winner, verbatim). Warps 0-3: consumers.
// Warps 4-7: producers (cp.async fp32 staging -> LDS -> split -> bf16 planes).
// Output: single fp16 plane.
// ---------------------------------------------------------------------------
__global__ __launch_bounds__(256, 1) void attn_bf16x3(
    const float* __restrict__ cache_k, const float* __restrict__ cache_v)
{
    extern __shared__ char smraw[];
    __nv_bfloat16* Kh = (__nv_bfloat16*)smraw;      // [2][64][136]
    __nv_bfloat16* Kl = Kh + 2*8704;
    __nv_bfloat16* Vh = Kl + 2*8704;
    __nv_bfloat16* Vl = Vh + 2*8704;                // planes end at 139264 B
    float* Kst = (float*)(smraw + 139264);          // staging [64][128] fp32
    float* Vst = (float*)(smraw + 172032);          // staging [64][128] fp32
    float* Qs  = (float*)smraw;                     // staging only (pre-loop)

    const int tid = threadIdx.x, lane = tid & 31, w = tid >> 5;
    const int g = lane >> 2, tig = lane & 3;
    const int lr = lane & 7, mt = lane >> 3;
    const int b = blockIdx.x >> 3, kvh = blockIdx.x & 7;
    const int ptid = tid & 127;
    const float scale = 0.08838834764831843f;       // 1/sqrt(128)
    const float* qkv = g_qkv;

    const uint32_t stk_b = (uint32_t)__cvta_generic_to_shared(Kst);
    const uint32_t stv_b = (uint32_t)__cvta_generic_to_shared(Vst);

    auto issue = [&](int t) {
        #pragma unroll
        for (int i = 0; i < 16; ++i) {
            int id = ptid + 128 * i;
            int row = id >> 5, c4 = (id & 31) << 2;
            int key = t * 64 + row;
            const float *ks, *vs;
            if (key < STARTP) {
                size_t base = ((size_t)(b * 4096 + key) * 8 + kvh) * 128 + c4;
                ks = cache_k + base; vs = cache_v + base;
            } else {
                size_t rb = (size_t)(b * 16 + key - STARTP) * 6144 + kvh * 128 + c4;
                ks = qkv + rb + 4096; vs = qkv + rb + 5120;
            }
            uint32_t off = (uint32_t)((row * 128 + c4) * 4);
            cp16(stk_b + off, ks);
            cp16(stv_b + off, vs);
        }
        asm volatile("cp.async.commit_group;");
    };
    auto convert = [&](int t) {
        int s = t & 1;
        #pragma unroll 4
        for (int i = 0; i < 16; ++i) {
            int id = ptid + 128 * i;
            int row = id >> 5, c4 = (id & 31) << 2;
            float4 kv = *(const float4*)&Kst[row * 128 + c4];
            float4 vv = *(const float4*)&Vst[row * 128 + c4];
            uint32_t h0, l0, h1, l1;
            int e = s * 8704 + row * 136 + c4;
            split2(kv.x, kv.y, h0, l0); split2(kv.z, kv.w, h1, l1);
            *(uint32_t*)&Kh[e] = h0; *(uint32_t*)&Kh[e + 2] = h1;
            *(uint32_t*)&Kl[e] = l0; *(uint32_t*)&Kl[e + 2] = l1;
            split2(vv.x, vv.y, h0, l0); split2(vv.z, vv.w, h1, l1);
            *(uint32_t*)&Vh[e] = h0; *(uint32_t*)&Vh[e + 2] = h1;
            *(uint32_t*)&Vl[e] = l0; *(uint32_t*)&Vl[e + 2] = l1;
        }
    };

    if (w >= 4) issue(0);

    if (w < 4) {
        for (int i = tid; i < 64 * 32; i += 128) {
            int r = i >> 5, c4 = (i & 31) << 2;
            const float* src = qkv + (size_t)(b * 16 + (r & 15)) * 6144
                             + (kvh * 4 + (r >> 4)) * 128 + c4;
            float4 v = *(const float4*)src;
            Qs[r * 132 + c4 + 0] = v.x * scale;
            Qs[r * 132 + c4 + 1] = v.y * scale;
            Qs[r * 132 + c4 + 2] = v.z * scale;
            Qs[r * 132 + c4 + 3] = v.w * scale;
        }
    }
    __syncthreads();

    uint32_t qh[8][4], ql[8][4];
    if (w < 4) {
        #pragma unroll
        for (int kk = 0; kk < 8; ++kk) {
            const float* r0 = Qs + (w*16 + g    ) * 132 + kk*16;
            const float* r1 = Qs + (w*16 + g + 8) * 132 + kk*16;
            split2(r0[2*tig],     r0[2*tig + 1], qh[kk][0], ql[kk][0]);
            split2(r1[2*tig],     r1[2*tig + 1], qh[kk][1], ql[kk][1]);
            split2(r0[2*tig + 8], r0[2*tig + 9], qh[kk][2], ql[kk][2]);
            split2(r1[2*tig + 8], r1[2*tig + 9], qh[kk][3], ql[kk][3]);
        }
    }
    __syncthreads();

    if (w >= 4) {
        asm volatile("cp.async.wait_group 0;");
        convert(0);
        issue(1);
    }
    __syncthreads();

    const uint32_t kh_b = (uint32_t)__cvta_generic_to_shared(Kh);
    const uint32_t kl_b = (uint32_t)__cvta_generic_to_shared(Kl);
    const uint32_t vh_b = (uint32_t)__cvta_generic_to_shared(Vh);
    const uint32_t vl_b = (uint32_t)__cvta_generic_to_shared(Vl);

    float oacc[16][4];
    #pragma unroll
    for (int i = 0; i < 16; ++i)
        #pragma unroll
        for (int j = 0; j < 4; ++j) oacc[i][j] = 0.f;
    float mA = -1e30f, mB = -1e30f, lA = 0.f, lB = 0.f;

    for (int t = 0; t < 64; ++t) {
        const int s = t & 1;

        if (w >= 4) {
            if (t + 1 < 64) {
                asm volatile("cp.async.wait_group 0;");
                convert(t + 1);
                if (t + 2 < 64) issue(t + 2);
            }
        } else {
            float sacc[8][4];
            #pragma unroll
            for (int nf = 0; nf < 8; ++nf)
                #pragma unroll
                for (int j = 0; j < 4; ++j) sacc[nf][j] = 0.f;

            #pragma unroll
            for (int kk = 0; kk < 8; ++kk) {
                #pragma unroll
                for (int nfp = 0; nfp < 4; ++nfp) {
                    int row = (nfp*2 + (mt >> 1))*8 + lr;
                    int col = kk*16 + (mt & 1)*8;
                    uint32_t off = (uint32_t)((s*8704 + row*136 + col)*2);
                    uint32_t bh[4], bl[4];
                    ldsm4(bh, kh_b + off);
                    ldsm4(bl, kl_b + off);
                    #pragma unroll
                    for (int h = 0; h < 2; ++h) {
                        int nf = nfp*2 + h;
                        mma16(sacc[nf], qh[kk], bh[2*h], bh[2*h+1]);
                        mma16(sacc[nf], qh[kk], bl[2*h], bl[2*h+1]);
                        mma16(sacc[nf], ql[kk], bh[2*h], bh[2*h+1]);
                    }
                }
            }

            if (t == 63) {
                #pragma unroll
                for (int nf = 0; nf < 8; ++nf) {
                    int key = 4032 + nf * 8 + 2 * tig;
                    if (key     > STARTP + g)     sacc[nf][0] = -1e30f;
                    if (key + 1 > STARTP + g)     sacc[nf][1] = -1e30f;
                    if (key     > STARTP + g + 8) sacc[nf][2] = -1e30f;
                    if (key + 1 > STARTP + g + 8) sacc[nf][3] = -1e30f;
                }
            }

            float tmA = -1e30f, tmB = -1e30f;
            #pragma unroll
            for (int nf = 0; nf < 8; ++nf) {
                tmA = fmaxf(tmA, fmaxf(sacc[nf][0], sacc[nf][1]));
                tmB = fmaxf(tmB, fmaxf(sacc[nf][2], sacc[nf][3]));
            }
            tmA = fmaxf(tmA, __shfl_xor_sync(0xffffffffu, tmA, 1));
            tmA = fmaxf(tmA, __shfl_xor_sync(0xffffffffu, tmA, 2));
            tmB = fmaxf(tmB, __shfl_xor_sync(0xffffffffu, tmB, 1));
            tmB = fmaxf(tmB, __shfl_xor_sync(0xffffffffu, tmB, 2));

            float mnA = fmaxf(mA, tmA), mnB = fmaxf(mB, tmB);
            float cA = __expf(mA - mnA), cB = __expf(mB - mnB);
            float psA = 0.f, psB = 0.f;
            #pragma unroll
            for (int nf = 0; nf < 8; ++nf) {
                sacc[nf][0] = __expf(sacc[nf][0] - mnA);
                sacc[nf][1] = __expf(sacc[nf][1] - mnA);
                sacc[nf][2] = __expf(sacc[nf][2] - mnB);
                sacc[nf][3] = __expf(sacc[nf][3] - mnB);
                psA += sacc[nf][0] + sacc[nf][1];
                psB += sacc[nf][2] + sacc[nf][3];
            }
            psA += __shfl_xor_sync(0xffffffffu, psA, 1);
            psA += __shfl_xor_sync(0xffffffffu, psA, 2);
            psB += __shfl_xor_sync(0xffffffffu, psB, 1);
            psB += __shfl_xor_sync(0xffffffffu, psB, 2);
            lA = lA * cA + psA; lB = lB * cB + psB;
            mA = mnA; mB = mnB;
            #pragma unroll
            for (int i = 0; i < 16; ++i) {
                oacc[i][0] *= cA; oacc[i][1] *= cA;
                oacc[i][2] *= cB; oacc[i][3] *= cB;
            }

            #pragma unroll
            for (int kf = 0; kf < 4; ++kf) {
                uint32_t pah[4], pal[4];
                split2(sacc[2*kf][0],   sacc[2*kf][1],   pah[0], pal[0]);
                split2(sacc[2*kf][2],   sacc[2*kf][3],   pah[1], pal[1]);
                split2(sacc[2*kf+1][0], sacc[2*kf+1][1], pah[2], pal[2]);
                split2(sacc[2*kf+1][2], sacc[2*kf+1][3], pah[3], pal[3]);
                #pragma unroll
                for (int np = 0; np < 8; ++np) {
                    int row = kf*16 + (mt & 1)*8 + lr;
                    int col = (np*2 + (mt >> 1))*8;
                    uint32_t off = (uint32_t)((s*8704 + row*136 + col)*2);
                    uint32_t vh[4], vl[4];
                    ldsm4t(vh, vh_b + off);
                    ldsm4t(vl, vl_b + off);
                    #pragma unroll
                    for (int h = 0; h < 2; ++h) {
                        int nf2 = np*2 + h;
                        mma16(oacc[nf2], pah, vh[2*h], vh[2*h+1]);
                        mma16(oacc[nf2], pah, vl[2*h], vl[2*h+1]);
                        mma16(oacc[nf2], pal, vh[2*h], vh[2*h+1]);
                    }
                }
            }
        }
        __syncthreads();
    }

    if (w < 4) {
        float rAi = 1.f / lA, rBi = 1.f / lB;
        size_t baseA = (size_t)(b*16 + g    ) * 4096 + (kvh*4 + w) * 128;
        size_t baseB = (size_t)(b*16 + g + 8) * 4096 + (kvh*4 + w) * 128;
        #pragma unroll
        for (int nf2 = 0; nf2 < 16; ++nf2) {
            int col = nf2*8 + 2*tig;
            *(uint32_t*)&g_at_h[baseA + col] =
                packh(oacc[nf2][0]*rAi, oacc[nf2][1]*rAi);
            *(uint32_t*)&g_at_h[baseB + col] =
                packh(oacc[nf2][2]*rBi, oacc[nf2][3]*rBi);
        }
    }
}

// ---------------------------------------------------------------------------
extern "C" void kernel_launch(void* const* d_in, const int* in_sizes, int n_in,
                              void* d_out, int out_size)
{
    const float* x  = (const float*)d_in[0];
    const float* fc = (const float*)d_in[1];
    const float* fs = (const float*)d_in[2];
    const float* ck = (const float*)d_in[4];
    const float* cv = (const float*)d_in[5];
    const float* wq = (const float*)d_in[6];
    const float* bq = (const float*)d_in[7];
    const float* wk = (const float*)d_in[8];
    const float* bk = (const float*)d_in[9];
    const float* wv = (const float*)d_in[10];
    const float* bv = (const float*)d_in[11];
    const float* wo = (const float*)d_in[12];
    const float* bo = (const float*)d_in[13];
    float* out = (float*)d_out;

    __half *x_h, *at_h;
    float* qkv;
    cudaGetSymbolAddress((void**)&x_h,  g_x_h);
    cudaGetSymbolAddress((void**)&at_h, g_at_h);
    cudaGetSymbolAddress((void**)&qkv,  g_qkv);

    const int gemm_smem = (2*64*40 + 2*32*72) * 2;        // 19456 B
    const int attn_smem = 139264 + 2 * 32768;             // 204800 B
    cudaFuncSetAttribute(gemm_f16x1<true>,
                         cudaFuncAttributeMaxDynamicSharedMemorySize, gemm_smem);
    cudaFuncSetAttribute(gemm_f16x1<false>,
                         cudaFuncAttributeMaxDynamicSharedMemorySize, gemm_smem);
    cudaFuncSetAttribute(attn_bf16x3,
                         cudaFuncAttributeMaxDynamicSharedMemorySize, attn_smem);

    // 1) x -> single fp16 plane
    convert_kernel<<<1024, 256>>>(x, x_h, 256*4096/4);

    // 2) fused QKV projection + RoPE (fp16x1; fp32 out into g_qkv); 384 blocks
    gemm_f16x1<true><<<dim3(96, 4), 128, gemm_smem>>>(
        x_h,
        wq, 4096, bq, 4096,
        wk, 1024, bk, 5120,
        wv, 1024, bv,
        qkv, 6144, fc, fs);

    // 3) attention (bf16x3, cp.async-staged producers; writes fp16 plane)
    attn_bf16x3<<<128, 256, attn_smem>>>(ck, cv);

    // 4) output projection (fp16x1) -> d_out; 256 blocks
    gemm_f16x1<false><<<dim3(64, 4), 128, gemm_smem>>>(
        at_h,
        wo, 4096, bo, 1 << 30,
        wo, 4096, bo, 1 << 30,
        wo, 4096, bo,
        out, 4096, nullptr, nullptr);
}